// round 10
// baseline (speedup 1.0000x reference)
#include <cuda_runtime.h>
#include <cuda_fp16.h>
#include <cstdint>

#define B_ROWS 8192
#define L_DIM  4096
#define OUT_DIM 512
#define SQRT_HALF 0.7071067811865476f

// ---------------- scratch (static __device__, no allocation) ----------------
__device__ __align__(128) float  g_F[(size_t)B_ROWS * L_DIM];    // fp32 coefficients
__device__ __align__(128) __half g_A16[(size_t)B_ROWS * L_DIM];  // masked fp16 A
__device__ __align__(128) __half g_B16[(size_t)OUT_DIM * L_DIM]; // B^T fp16 [n][k]
__device__ double g_pabs[B_ROWS];
__device__ double g_psq[B_ROWS];
__device__ float  g_thr;

// ---------------- PTX helpers (sm_80-baseline only) ----------------
__device__ __forceinline__ uint32_t smem_u32(const void* p) {
    uint32_t a;
    asm("{ .reg .u64 t; cvta.to.shared.u64 t, %1; cvt.u32.u64 %0, t; }" : "=r"(a) : "l"(p));
    return a;
}
__device__ __forceinline__ void cp16(uint32_t dst, const void* src) {
    asm volatile("cp.async.cg.shared.global [%0], [%1], 16;" :: "r"(dst), "l"(src) : "memory");
}
__device__ __forceinline__ void ldsm4(uint32_t* r, uint32_t addr) {
    asm volatile("ldmatrix.sync.aligned.m8n8.x4.shared.b16 {%0,%1,%2,%3}, [%4];"
                 : "=r"(r[0]), "=r"(r[1]), "=r"(r[2]), "=r"(r[3]) : "r"(addr));
}
__device__ __forceinline__ void mma16816(float* c, const uint32_t* a, const uint32_t* b) {
    asm volatile("mma.sync.aligned.m16n8k16.row.col.f32.f16.f16.f32 "
                 "{%0,%1,%2,%3}, {%4,%5,%6,%7}, {%8,%9}, {%0,%1,%2,%3};"
                 : "+f"(c[0]), "+f"(c[1]), "+f"(c[2]), "+f"(c[3])
                 : "r"(a[0]), "r"(a[1]), "r"(a[2]), "r"(a[3]), "r"(b[0]), "r"(b[1]));
}
__device__ __forceinline__ uint32_t packh(float a, float b) {
    __half2 h = __floats2half2_rn(a, b);
    return *reinterpret_cast<uint32_t*>(&h);
}

// ---------------- kernel 1: Haar DWT + per-row stats ----------------
__global__ __launch_bounds__(256) void haar_kernel(const float* __restrict__ x) {
    __shared__ float s[4096];
    __shared__ double wa[8], wq[8];

    const int r = blockIdx.x;
    const int tid = threadIdx.x;

    const float4* xr = reinterpret_cast<const float4*>(x + (size_t)r * L_DIM);
    float4* s4 = reinterpret_cast<float4*>(s);
    #pragma unroll
    for (int i = 0; i < 4; i++) s4[tid + i * 256] = xr[tid + i * 256];
    __syncthreads();

    float sabs = 0.f, ssq = 0.f;
    float* Fr = g_F + (size_t)r * L_DIM;

    #pragma unroll
    for (int lvl = 0; lvl < 5; lvl++) {
        const int half = 2048 >> lvl;
        float areg[8];
        #pragma unroll
        for (int it = 0; it < 8; it++) {
            const int t = tid + it * 256;
            if (t < half) {
                float2 eo = *reinterpret_cast<const float2*>(&s[2 * t]);
                float d = (eo.x - eo.y) * SQRT_HALF;
                float a = (eo.x + eo.y) * SQRT_HALF;
                Fr[half + t] = d;
                sabs += fabsf(d);
                ssq  += d * d;
                areg[it] = a;
            }
        }
        __syncthreads();
        #pragma unroll
        for (int it = 0; it < 8; it++) {
            const int t = tid + it * 256;
            if (t < half) s[t] = areg[it];
        }
        __syncthreads();
    }
    if (tid < 128) {
        float a = s[tid];
        Fr[tid] = a;
        sabs += fabsf(a);
        ssq  += a * a;
    }

    double da = (double)sabs, dq = (double)ssq;
    #pragma unroll
    for (int o = 16; o > 0; o >>= 1) {
        da += __shfl_down_sync(0xffffffffu, da, o);
        dq += __shfl_down_sync(0xffffffffu, dq, o);
    }
    const int w = tid >> 5, ln = tid & 31;
    if (ln == 0) { wa[w] = da; wq[w] = dq; }
    __syncthreads();
    if (tid == 0) {
        double A = 0.0, Q = 0.0;
        #pragma unroll
        for (int i = 0; i < 8; i++) { A += wa[i]; Q += wq[i]; }
        g_pabs[r] = A;
        g_psq[r]  = Q;
    }
}

// ---------------- kernel 2: global threshold ----------------
__global__ __launch_bounds__(256) void thr_kernel() {
    __shared__ double wa[8], wq[8];
    const int tid = threadIdx.x;
    double da = 0.0, dq = 0.0;
    for (int i = tid; i < B_ROWS; i += 256) { da += g_pabs[i]; dq += g_psq[i]; }
    #pragma unroll
    for (int o = 16; o > 0; o >>= 1) {
        da += __shfl_down_sync(0xffffffffu, da, o);
        dq += __shfl_down_sync(0xffffffffu, dq, o);
    }
    const int w = tid >> 5, ln = tid & 31;
    if (ln == 0) { wa[w] = da; wq[w] = dq; }
    __syncthreads();
    if (tid == 0) {
        double A = 0.0, Q = 0.0;
        #pragma unroll
        for (int i = 0; i < 8; i++) { A += wa[i]; Q += wq[i]; }
        const double N = (double)B_ROWS * (double)L_DIM;
        double mean = A / N;
        double var  = (Q - N * mean * mean) / (N - 1.0);
        if (var < 0.0) var = 0.0;
        g_thr = (float)(mean + sqrt(var));
    }
}

// ---------------- kernel 2b: mask + fp16 convert of A (streaming) ----------------
__global__ __launch_bounds__(256) void amask_kernel() {
    const float thr = g_thr;
    const size_t i = ((size_t)blockIdx.x * 256 + threadIdx.x) * 8;
    float4 v0 = *reinterpret_cast<const float4*>(g_F + i);
    float4 v1 = *reinterpret_cast<const float4*>(g_F + i + 4);
    v0.x = (fabsf(v0.x) > thr) ? v0.x : 0.f;
    v0.y = (fabsf(v0.y) > thr) ? v0.y : 0.f;
    v0.z = (fabsf(v0.z) > thr) ? v0.z : 0.f;
    v0.w = (fabsf(v0.w) > thr) ? v0.w : 0.f;
    v1.x = (fabsf(v1.x) > thr) ? v1.x : 0.f;
    v1.y = (fabsf(v1.y) > thr) ? v1.y : 0.f;
    v1.z = (fabsf(v1.z) > thr) ? v1.z : 0.f;
    v1.w = (fabsf(v1.w) > thr) ? v1.w : 0.f;
    uint4 o;
    o.x = packh(v0.x, v0.y);
    o.y = packh(v0.z, v0.w);
    o.z = packh(v1.x, v1.y);
    o.w = packh(v1.z, v1.w);
    *reinterpret_cast<uint4*>(g_A16 + i) = o;
}

// ---------------- kernel 3: B transpose + fp16 convert ----------------
__global__ __launch_bounds__(256) void bconv_kernel(const float* __restrict__ Bm) {
    __shared__ float t[64][65];
    const int n0 = blockIdx.x * 64;
    const int k0 = blockIdx.y * 64;
    for (int idx = threadIdx.x; idx < 4096; idx += 256) {
        int r = idx >> 6, c = idx & 63;           // r = k, c = n
        t[r][c] = Bm[(size_t)(k0 + r) * OUT_DIM + n0 + c];
    }
    __syncthreads();
    for (int idx = threadIdx.x; idx < 4096; idx += 256) {
        int n = idx >> 6, kk = idx & 63;
        g_B16[(size_t)(n0 + n) * L_DIM + k0 + kk] = __float2half_rn(t[kk][n]);
    }
}

// ---------------- kernel 4: fp16 HMMA GEMM + ReLU (3-stage cp.async pipeline) ----------------
// CTA 128(m) x 256(n) x 64(k), 512 threads, 16 warps = 4m x 4n, warp tile 32x64.
#define BM 128
#define BN 256
#define BK 64
#define NST (L_DIM / BK)
#define PADA 144
#define PADB 144
#define A_SZ (128 * PADA)                          /* 18432 */
#define B_SZ (256 * PADB)                          /* 36864 */
#define ST_SZ (A_SZ + B_SZ)                        /* 55296 */
#define OFF_A(b) ((b) * ST_SZ)
#define OFF_B(b) ((b) * ST_SZ + A_SZ)
#define SMEM_TOTAL (3 * ST_SZ)                     /* 165888 */

__global__ void __launch_bounds__(512, 1) gemm_kernel(float* __restrict__ out) {
    extern __shared__ char smem[];
    const uint32_t sb = smem_u32(smem);
    const int tid = threadIdx.x;
    const int lane = tid & 31;
    const int wid = tid >> 5;
    const int bm = blockIdx.y * BM;
    const int bn = blockIdx.x * BN;

    const int wm = (wid >> 2) * 32;               // warp m-offset
    const int wn = (wid & 3) * 64;                // warp n-offset

    // cp.async mappings
    const int a_r = tid >> 2, a_c = (tid & 3) * 32;   // A: 128 rows x 128B; 2x16B per thread
    const int b_r = tid >> 1, b_c = (tid & 1) * 64;   // B: 256 rows x 128B; 4x16B per thread

    const char* Asrc = (const char*)(g_A16 + (size_t)(bm + a_r) * L_DIM) + a_c;
    const char* Bsrc = (const char*)(g_B16 + (size_t)(bn + b_r) * L_DIM) + b_c;

    float acc[2][8][4];
    #pragma unroll
    for (int i = 0; i < 2; i++)
        #pragma unroll
        for (int j = 0; j < 8; j++)
            #pragma unroll
            for (int q = 0; q < 4; q++) acc[i][j][q] = 0.f;

    // ---- fill a stage's buffers ----
    auto fill = [&](int buf, int kbytes) {
        cp16(sb + OFF_A(buf) + a_r * PADA + a_c,      Asrc + kbytes);
        cp16(sb + OFF_A(buf) + a_r * PADA + a_c + 16, Asrc + kbytes + 16);
        #pragma unroll
        for (int i = 0; i < 4; i++)
            cp16(sb + OFF_B(buf) + b_r * PADB + b_c + i * 16, Bsrc + kbytes + i * 16);
        asm volatile("cp.async.commit_group;" ::: "memory");
    };

    // ---- prologue: stage 0 and 1 in flight ----
    fill(0, 0);
    fill(1, BK * 2);
    asm volatile("cp.async.wait_group 1;" ::: "memory");
    __syncthreads();

    for (int s = 0; s < NST; s++) {
        const int b = s % 3;

        if (s + 2 < NST) fill((s + 2) % 3, (s + 2) * BK * 2);

        // ---- compute on buffer b ----
        const uint32_t sAH = sb + OFF_A(b);
        const uint32_t sBH = sb + OFF_B(b);
        #pragma unroll
        for (int ks = 0; ks < 4; ks++) {
            const uint32_t ab = ks * 32 + ((lane >> 4) << 4);
            const uint32_t ar = wm + (lane & 15);
            const uint32_t bb = ks * 32 + (((lane >> 3) & 1) << 4);
            const uint32_t br = ((lane >> 4) << 3) + (lane & 7);

            uint32_t bh[4][4];
            #pragma unroll
            for (int g = 0; g < 4; g++)
                ldsm4(bh[g], sBH + (wn + g * 16 + br) * PADB + bb);

            uint32_t ah[2][4];
            ldsm4(ah[0], sAH + ar * PADA + ab);
            ldsm4(ah[1], sAH + (ar + 16) * PADA + ab);

            #pragma unroll
            for (int mf = 0; mf < 2; mf++)
                #pragma unroll
                for (int g = 0; g < 4; g++) {
                    mma16816(acc[mf][2 * g],     ah[mf], &bh[g][0]);
                    mma16816(acc[mf][2 * g + 1], ah[mf], &bh[g][2]);
                }
        }

        // ensure next stage's buffer is complete before the barrier releases it
        if (s + 2 < NST) {
            asm volatile("cp.async.wait_group 1;" ::: "memory");
        } else {
            asm volatile("cp.async.wait_group 0;" ::: "memory");
        }
        __syncthreads();
    }

    // ---- epilogue: ReLU + store ----
    const int g  = lane >> 2;
    const int tq = lane & 3;
    #pragma unroll
    for (int mf = 0; mf < 2; mf++) {
        #pragma unroll
        for (int nf = 0; nf < 8; nf++) {
            const int m0 = bm + wm + mf * 16 + g;
            const int n0 = bn + wn + nf * 8 + tq * 2;
            float2 v0, v1;
            v0.x = fmaxf(acc[mf][nf][0], 0.f);
            v0.y = fmaxf(acc[mf][nf][1], 0.f);
            v1.x = fmaxf(acc[mf][nf][2], 0.f);
            v1.y = fmaxf(acc[mf][nf][3], 0.f);
            *reinterpret_cast<float2*>(out + (size_t)m0 * OUT_DIM + n0) = v0;
            *reinterpret_cast<float2*>(out + (size_t)(m0 + 8) * OUT_DIM + n0) = v1;
        }
    }
}

// ---------------- launcher ----------------
extern "C" void kernel_launch(void* const* d_in, const int* in_sizes, int n_in,
                              void* d_out, int out_size) {
    const float* x  = (const float*)d_in[0];     // (8192, 1, 4096) fp32
    const float* bm = (const float*)d_in[1];     // (4096, 512) fp32
    float* out = (float*)d_out;                  // (8192, 1, 512) fp32

    cudaFuncSetAttribute(gemm_kernel, cudaFuncAttributeMaxDynamicSharedMemorySize, SMEM_TOTAL);

    haar_kernel<<<B_ROWS, 256>>>(x);
    thr_kernel<<<1, 256>>>();
    bconv_kernel<<<dim3(OUT_DIM / 64, L_DIM / 64), 256>>>(bm);
    amask_kernel<<<(B_ROWS * (L_DIM / 8)) / 256, 256>>>();   // 16384 blocks
    gemm_kernel<<<dim3(OUT_DIM / BN, B_ROWS / BM), 512, SMEM_TOTAL>>>(out);
}

// round 12
// speedup vs baseline: 1.0015x; 1.0015x over previous
#include <cuda_runtime.h>
#include <cuda_fp16.h>
#include <cstdint>

#define B_ROWS 8192
#define L_DIM  4096
#define OUT_DIM 512
#define SQRT_HALF 0.7071067811865476f

// ---------------- scratch (static __device__, no allocation) ----------------
__device__ __align__(128) __half g_A16[(size_t)B_ROWS * L_DIM];  // masked fp16 A
__device__ __align__(128) __half g_B16[(size_t)OUT_DIM * L_DIM]; // B^T fp16 [n][k]
__device__ double g_pabs[B_ROWS];
__device__ double g_psq[B_ROWS];
__device__ float  g_thr;

// ---------------- PTX helpers ----------------
__device__ __forceinline__ uint32_t smem_u32(const void* p) {
    uint32_t a;
    asm("{ .reg .u64 t; cvta.to.shared.u64 t, %1; cvt.u32.u64 %0, t; }" : "=r"(a) : "l"(p));
    return a;
}
__device__ __forceinline__ void ldsm4(uint32_t* r, uint32_t addr) {
    asm volatile("ldmatrix.sync.aligned.m8n8.x4.shared.b16 {%0,%1,%2,%3}, [%4];"
                 : "=r"(r[0]), "=r"(r[1]), "=r"(r[2]), "=r"(r[3]) : "r"(addr));
}
__device__ __forceinline__ void mma16816(float* c, const uint32_t* a, const uint32_t* b) {
    asm volatile("mma.sync.aligned.m16n8k16.row.col.f32.f16.f16.f32 "
                 "{%0,%1,%2,%3}, {%4,%5,%6,%7}, {%8,%9}, {%0,%1,%2,%3};"
                 : "+f"(c[0]), "+f"(c[1]), "+f"(c[2]), "+f"(c[3])
                 : "r"(a[0]), "r"(a[1]), "r"(a[2]), "r"(a[3]), "r"(b[0]), "r"(b[1]));
}
__device__ __forceinline__ uint32_t packh(float a, float b) {
    __half2 h = __floats2half2_rn(a, b);
    return *reinterpret_cast<uint32_t*>(&h);
}
// single-instruction 128B async bulk copy global->shared with mbarrier tx accounting
__device__ __forceinline__ void bulk128(uint32_t dst, const void* src, uint32_t mbar) {
    asm volatile("cp.async.bulk.shared::cluster.global.mbarrier::complete_tx::bytes "
                 "[%0], [%1], 128, [%2];"
                 :: "r"(dst), "l"(src), "r"(mbar) : "memory");
}
__device__ __forceinline__ void mbar_init(uint32_t a, uint32_t c) {
    asm volatile("mbarrier.init.shared.b64 [%0], %1;" :: "r"(a), "r"(c) : "memory");
}
__device__ __forceinline__ void mbar_expect(uint32_t a, uint32_t bytes) {
    asm volatile("mbarrier.arrive.expect_tx.shared.b64 _, [%0], %1;" :: "r"(a), "r"(bytes) : "memory");
}
__device__ __forceinline__ void mbar_wait(uint32_t mbar, uint32_t parity) {
    uint32_t done;
    asm volatile("{\n\t.reg .pred p;\n\tmbarrier.try_wait.parity.acquire.cta.shared::cta.b64 p, [%1], %2;\n\tselp.b32 %0, 1, 0, p;\n\t}"
                 : "=r"(done) : "r"(mbar), "r"(parity) : "memory");
    if (!done) {
        asm volatile("{\n\t.reg .pred P1;\n\tWL_%=:\n\tmbarrier.try_wait.parity.acquire.cta.shared::cta.b64 P1, [%0], %1, 0x989680;\n\t@P1 bra.uni WD_%=;\n\tbra.uni WL_%=;\n\tWD_%=:\n\t}"
                     :: "r"(mbar), "r"(parity) : "memory");
    }
}

// ---------------- kernel 1: Haar DWT, stats ONLY (no coefficient store) ----------------
__global__ __launch_bounds__(256) void haar_stats_kernel(const float* __restrict__ x) {
    __shared__ float s[4096];
    __shared__ double wa[8], wq[8];

    const int r = blockIdx.x;
    const int tid = threadIdx.x;

    const float4* xr = reinterpret_cast<const float4*>(x + (size_t)r * L_DIM);
    float4* s4 = reinterpret_cast<float4*>(s);
    #pragma unroll
    for (int i = 0; i < 4; i++) s4[tid + i * 256] = xr[tid + i * 256];
    __syncthreads();

    float sabs = 0.f, ssq = 0.f;

    #pragma unroll
    for (int lvl = 0; lvl < 5; lvl++) {
        const int half = 2048 >> lvl;
        float areg[8];
        #pragma unroll
        for (int it = 0; it < 8; it++) {
            const int t = tid + it * 256;
            if (t < half) {
                float2 eo = *reinterpret_cast<const float2*>(&s[2 * t]);
                float d = (eo.x - eo.y) * SQRT_HALF;
                float a = (eo.x + eo.y) * SQRT_HALF;
                sabs += fabsf(d);
                ssq  += d * d;
                areg[it] = a;
            }
        }
        __syncthreads();
        #pragma unroll
        for (int it = 0; it < 8; it++) {
            const int t = tid + it * 256;
            if (t < half) s[t] = areg[it];
        }
        __syncthreads();
    }
    if (tid < 128) {
        float a = s[tid];
        sabs += fabsf(a);
        ssq  += a * a;
    }

    double da = (double)sabs, dq = (double)ssq;
    #pragma unroll
    for (int o = 16; o > 0; o >>= 1) {
        da += __shfl_down_sync(0xffffffffu, da, o);
        dq += __shfl_down_sync(0xffffffffu, dq, o);
    }
    const int w = tid >> 5, ln = tid & 31;
    if (ln == 0) { wa[w] = da; wq[w] = dq; }
    __syncthreads();
    if (tid == 0) {
        double A = 0.0, Q = 0.0;
        #pragma unroll
        for (int i = 0; i < 8; i++) { A += wa[i]; Q += wq[i]; }
        g_pabs[r] = A;
        g_psq[r]  = Q;
    }
}

// ---------------- kernel 2: global threshold ----------------
__global__ __launch_bounds__(256) void thr_kernel() {
    __shared__ double wa[8], wq[8];
    const int tid = threadIdx.x;
    double da = 0.0, dq = 0.0;
    for (int i = tid; i < B_ROWS; i += 256) { da += g_pabs[i]; dq += g_psq[i]; }
    #pragma unroll
    for (int o = 16; o > 0; o >>= 1) {
        da += __shfl_down_sync(0xffffffffu, da, o);
        dq += __shfl_down_sync(0xffffffffu, dq, o);
    }
    const int w = tid >> 5, ln = tid & 31;
    if (ln == 0) { wa[w] = da; wq[w] = dq; }
    __syncthreads();
    if (tid == 0) {
        double A = 0.0, Q = 0.0;
        #pragma unroll
        for (int i = 0; i < 8; i++) { A += wa[i]; Q += wq[i]; }
        const double N = (double)B_ROWS * (double)L_DIM;
        double mean = A / N;
        double var  = (Q - N * mean * mean) / (N - 1.0);
        if (var < 0.0) var = 0.0;
        g_thr = (float)(mean + sqrt(var));
    }
}

// ---------------- kernel 3: Haar recompute + mask + fp16 store ----------------
__global__ __launch_bounds__(256) void haar_mask_kernel(const float* __restrict__ x) {
    __shared__ float s[4096];
    __shared__ __half o16[4096];

    const int r = blockIdx.x;
    const int tid = threadIdx.x;
    const float thr = g_thr;

    const float4* xr = reinterpret_cast<const float4*>(x + (size_t)r * L_DIM);
    float4* s4 = reinterpret_cast<float4*>(s);
    #pragma unroll
    for (int i = 0; i < 4; i++) s4[tid + i * 256] = xr[tid + i * 256];
    __syncthreads();

    #pragma unroll
    for (int lvl = 0; lvl < 5; lvl++) {
        const int half = 2048 >> lvl;
        float areg[8];
        #pragma unroll
        for (int it = 0; it < 8; it++) {
            const int t = tid + it * 256;
            if (t < half) {
                float2 eo = *reinterpret_cast<const float2*>(&s[2 * t]);
                float d = (eo.x - eo.y) * SQRT_HALF;
                float a = (eo.x + eo.y) * SQRT_HALF;
                float dm = (fabsf(d) > thr) ? d : 0.f;
                o16[half + t] = __float2half_rn(dm);
                areg[it] = a;
            }
        }
        __syncthreads();
        #pragma unroll
        for (int it = 0; it < 8; it++) {
            const int t = tid + it * 256;
            if (t < half) s[t] = areg[it];
        }
        __syncthreads();
    }
    if (tid < 128) {
        float a = s[tid];
        float am = (fabsf(a) > thr) ? a : 0.f;
        o16[tid] = __float2half_rn(am);
    }
    __syncthreads();

    // vectorized copy out: 8 KB row
    const uint4* src = reinterpret_cast<const uint4*>(o16);
    uint4* dst = reinterpret_cast<uint4*>(g_A16 + (size_t)r * L_DIM);
    #pragma unroll
    for (int i = 0; i < 2; i++) dst[tid + i * 256] = src[tid + i * 256];
}

// ---------------- kernel 4: B transpose + fp16 convert ----------------
__global__ __launch_bounds__(256) void bconv_kernel(const float* __restrict__ Bm) {
    __shared__ float t[64][65];
    const int n0 = blockIdx.x * 64;
    const int k0 = blockIdx.y * 64;
    for (int idx = threadIdx.x; idx < 4096; idx += 256) {
        int r = idx >> 6, c = idx & 63;           // r = k, c = n
        t[r][c] = Bm[(size_t)(k0 + r) * OUT_DIM + n0 + c];
    }
    __syncthreads();
    for (int idx = threadIdx.x; idx < 4096; idx += 256) {
        int n = idx >> 6, kk = idx & 63;
        g_B16[(size_t)(n0 + n) * L_DIM + k0 + kk] = __float2half_rn(t[kk][n]);
    }
}

// ---------------- kernel 5: fp16 HMMA GEMM + ReLU (bulk-copy 3-stage pipeline) ----------------
// CTA 128(m) x 256(n) x 64(k), 512 threads, 16 warps = 4m x 4n, warp tile 32x64.
// Tiles loaded with cp.async.bulk (128B per row-copy) + mbarrier tx accounting:
// 384 copy instructions per stage instead of 3072 cp.async.cg.
#define BM 128
#define BN 256
#define BK 64
#define NST (L_DIM / BK)
#define PADA 144
#define PADB 144
#define A_SZ (128 * PADA)                          /* 18432 */
#define B_SZ (256 * PADB)                          /* 36864 */
#define ST_SZ (A_SZ + B_SZ)                        /* 55296 */
#define OFF_A(b) ((b) * ST_SZ)
#define OFF_B(b) ((b) * ST_SZ + A_SZ)
#define MBAR_OFF (3 * ST_SZ)                       /* 3 x 8B mbarriers */
#define SMEM_TOTAL (3 * ST_SZ + 64)                /* 165952 */
#define STAGE_BYTES (128 * 128 + 256 * 128)        /* 49152 */

__global__ void __launch_bounds__(512, 1) gemm_kernel(float* __restrict__ out) {
    extern __shared__ char smem[];
    const uint32_t sb = smem_u32(smem);
    const int tid = threadIdx.x;
    const int lane = tid & 31;
    const int wid = tid >> 5;
    const int bm = blockIdx.y * BM;
    const int bn = blockIdx.x * BN;

    const int wm = (wid >> 2) * 32;               // warp m-offset
    const int wn = (wid & 3) * 64;                // warp n-offset

    // ---- mbarrier init ----
    if (tid == 0) {
        mbar_init(sb + MBAR_OFF + 0, 12);
        mbar_init(sb + MBAR_OFF + 8, 12);
        mbar_init(sb + MBAR_OFF + 16, 12);
        asm volatile("fence.proxy.async.shared::cta;" ::: "memory");
    }
    __syncthreads();

    float acc[2][8][4];
    #pragma unroll
    for (int i = 0; i < 2; i++)
        #pragma unroll
        for (int j = 0; j < 8; j++)
            #pragma unroll
            for (int q = 0; q < 4; q++) acc[i][j][q] = 0.f;

    // fill stage t: warps 0-3 copy A rows (32 each), warps 4-11 copy B rows (32 each).
    // warp leader arrives with expect_tx = 32 rows * 128B = 4096.
    auto fill = [&](int t) {
        const int buf = t % 3;
        const uint32_t mb = sb + MBAR_OFF + buf * 8;
        const int k = t * BK;
        if (wid < 4) {
            if (lane == 0) mbar_expect(mb, 4096);
            const int r = wid * 32 + lane;
            bulk128(sb + OFF_A(buf) + r * PADA,
                    (const char*)(g_A16 + (size_t)(bm + r) * L_DIM + k), mb);
        } else if (wid < 12) {
            if (lane == 0) mbar_expect(mb, 4096);
            const int r = (wid - 4) * 32 + lane;
            bulk128(sb + OFF_B(buf) + r * PADB,
                    (const char*)(g_B16 + (size_t)(bn + r) * L_DIM + k), mb);
        }
    };

    // ---- prologue: stages 0 and 1 in flight ----
    fill(0);
    fill(1);

    for (int s = 0; s < NST; s++) {
        const int b = s % 3;

        if (s + 2 < NST) fill(s + 2);

        mbar_wait(sb + MBAR_OFF + b * 8, (uint32_t)((s / 3) & 1));

        // ---- compute on buffer b ----
        const uint32_t sAH = sb + OFF_A(b);
        const uint32_t sBH = sb + OFF_B(b);
        #pragma unroll
        for (int ks = 0; ks < 4; ks++) {
            const uint32_t ab = ks * 32 + ((lane >> 4) << 4);
            const uint32_t ar = wm + (lane & 15);
            const uint32_t bb = ks * 32 + (((lane >> 3) & 1) << 4);
            const uint32_t br = ((lane >> 4) << 3) + (lane & 7);

            uint32_t bh[4][4];
            #pragma unroll
            for (int g = 0; g < 4; g++)
                ldsm4(bh[g], sBH + (wn + g * 16 + br) * PADB + bb);

            uint32_t ah[2][4];
            ldsm4(ah[0], sAH + ar * PADA + ab);
            ldsm4(ah[1], sAH + (ar + 16) * PADA + ab);

            #pragma unroll
            for (int mf = 0; mf < 2; mf++)
                #pragma unroll
                for (int g = 0; g < 4; g++) {
                    mma16816(acc[mf][2 * g],     ah[mf], &bh[g][0]);
                    mma16816(acc[mf][2 * g + 1], ah[mf], &bh[g][2]);
                }
        }

        __syncthreads();
    }

    // ---- epilogue: ReLU + store ----
    const int g  = lane >> 2;
    const int tq = lane & 3;
    #pragma unroll
    for (int mf = 0; mf < 2; mf++) {
        #pragma unroll
        for (int nf = 0; nf < 8; nf++) {
            const int m0 = bm + wm + mf * 16 + g;
            const int n0 = bn + wn + nf * 8 + tq * 2;
            float2 v0, v1;
            v0.x = fmaxf(acc[mf][nf][0], 0.f);
            v0.y = fmaxf(acc[mf][nf][1], 0.f);
            v1.x = fmaxf(acc[mf][nf][2], 0.f);
            v1.y = fmaxf(acc[mf][nf][3], 0.f);
            *reinterpret_cast<float2*>(out + (size_t)m0 * OUT_DIM + n0) = v0;
            *reinterpret_cast<float2*>(out + (size_t)(m0 + 8) * OUT_DIM + n0) = v1;
        }
    }
}

// ---------------- launcher ----------------
extern "C" void kernel_launch(void* const* d_in, const int* in_sizes, int n_in,
                              void* d_out, int out_size) {
    const float* x  = (const float*)d_in[0];     // (8192, 1, 4096) fp32
    const float* bm = (const float*)d_in[1];     // (4096, 512) fp32
    float* out = (float*)d_out;                  // (8192, 1, 512) fp32

    cudaFuncSetAttribute(gemm_kernel, cudaFuncAttributeMaxDynamicSharedMemorySize, SMEM_TOTAL);

    haar_stats_kernel<<<B_ROWS, 256>>>(x);
    thr_kernel<<<1, 256>>>();
    bconv_kernel<<<dim3(OUT_DIM / 64, L_DIM / 64), 256>>>(bm);
    haar_mask_kernel<<<B_ROWS, 256>>>(x);
    gemm_kernel<<<dim3(OUT_DIM / BN, B_ROWS / BM), 512, SMEM_TOTAL>>>(out);
}

// round 13
// speedup vs baseline: 1.2503x; 1.2485x over previous
#include <cuda_runtime.h>
#include <cuda_fp16.h>
#include <cuda.h>
#include <cstdint>

#define B_ROWS 8192
#define L_DIM  4096
#define OUT_DIM 512
#define SQRT_HALF 0.7071067811865476f

// ---------------- scratch (static __device__, no allocation) ----------------
__device__ __align__(128) __half g_A16[(size_t)B_ROWS * L_DIM];  // masked fp16 A
__device__ __align__(128) __half g_B16[(size_t)OUT_DIM * L_DIM]; // B^T fp16 [n][k]
__device__ double g_pabs[B_ROWS];
__device__ double g_psq[B_ROWS];
__device__ float  g_thr;

// ---------------- PTX helpers ----------------
__device__ __forceinline__ uint32_t smem_u32(const void* p) {
    uint32_t a;
    asm("{ .reg .u64 t; cvta.to.shared.u64 t, %1; cvt.u32.u64 %0, t; }" : "=r"(a) : "l"(p));
    return a;
}
__device__ __forceinline__ void ldsm4(uint32_t* r, uint32_t addr) {
    asm volatile("ldmatrix.sync.aligned.m8n8.x4.shared.b16 {%0,%1,%2,%3}, [%4];"
                 : "=r"(r[0]), "=r"(r[1]), "=r"(r[2]), "=r"(r[3]) : "r"(addr));
}
__device__ __forceinline__ void mma16816(float* c, const uint32_t* a, const uint32_t* b) {
    asm volatile("mma.sync.aligned.m16n8k16.row.col.f32.f16.f16.f32 "
                 "{%0,%1,%2,%3}, {%4,%5,%6,%7}, {%8,%9}, {%0,%1,%2,%3};"
                 : "+f"(c[0]), "+f"(c[1]), "+f"(c[2]), "+f"(c[3])
                 : "r"(a[0]), "r"(a[1]), "r"(a[2]), "r"(a[3]), "r"(b[0]), "r"(b[1]));
}
__device__ __forceinline__ void tma2d(uint32_t dst, const CUtensorMap* map,
                                      int cx, int cy, uint32_t mbar) {
    asm volatile("cp.async.bulk.tensor.2d.shared::cluster.global.tile.mbarrier::complete_tx::bytes "
                 "[%0], [%1, {%2, %3}], [%4];"
                 :: "r"(dst), "l"(map), "r"(cx), "r"(cy), "r"(mbar) : "memory");
}
__device__ __forceinline__ void mbar_init(uint32_t a, uint32_t c) {
    asm volatile("mbarrier.init.shared.b64 [%0], %1;" :: "r"(a), "r"(c) : "memory");
}
__device__ __forceinline__ void mbar_expect(uint32_t a, uint32_t bytes) {
    asm volatile("mbarrier.arrive.expect_tx.shared.b64 _, [%0], %1;" :: "r"(a), "r"(bytes) : "memory");
}
__device__ __forceinline__ void mbar_wait(uint32_t mbar, uint32_t parity) {
    uint32_t done;
    asm volatile("{\n\t.reg .pred p;\n\tmbarrier.try_wait.parity.acquire.cta.shared::cta.b64 p, [%1], %2;\n\tselp.b32 %0, 1, 0, p;\n\t}"
                 : "=r"(done) : "r"(mbar), "r"(parity) : "memory");
    if (!done) {
        asm volatile("{\n\t.reg .pred P1;\n\tWL_%=:\n\tmbarrier.try_wait.parity.acquire.cta.shared::cta.b64 P1, [%0], %1, 0x989680;\n\t@P1 bra.uni WD_%=;\n\tbra.uni WL_%=;\n\tWD_%=:\n\t}"
                     :: "r"(mbar), "r"(parity) : "memory");
    }
}

// ---------------- kernel 1: Haar DWT, stats ONLY ----------------
__global__ __launch_bounds__(256) void haar_stats_kernel(const float* __restrict__ x) {
    __shared__ float s[4096];
    __shared__ double wa[8], wq[8];

    const int r = blockIdx.x;
    const int tid = threadIdx.x;

    const float4* xr = reinterpret_cast<const float4*>(x + (size_t)r * L_DIM);
    float4* s4 = reinterpret_cast<float4*>(s);
    #pragma unroll
    for (int i = 0; i < 4; i++) s4[tid + i * 256] = xr[tid + i * 256];
    __syncthreads();

    float sabs = 0.f, ssq = 0.f;

    #pragma unroll
    for (int lvl = 0; lvl < 5; lvl++) {
        const int half = 2048 >> lvl;
        float areg[8];
        #pragma unroll
        for (int it = 0; it < 8; it++) {
            const int t = tid + it * 256;
            if (t < half) {
                float2 eo = *reinterpret_cast<const float2*>(&s[2 * t]);
                float d = (eo.x - eo.y) * SQRT_HALF;
                float a = (eo.x + eo.y) * SQRT_HALF;
                sabs += fabsf(d);
                ssq  += d * d;
                areg[it] = a;
            }
        }
        __syncthreads();
        #pragma unroll
        for (int it = 0; it < 8; it++) {
            const int t = tid + it * 256;
            if (t < half) s[t] = areg[it];
        }
        __syncthreads();
    }
    if (tid < 128) {
        float a = s[tid];
        sabs += fabsf(a);
        ssq  += a * a;
    }

    double da = (double)sabs, dq = (double)ssq;
    #pragma unroll
    for (int o = 16; o > 0; o >>= 1) {
        da += __shfl_down_sync(0xffffffffu, da, o);
        dq += __shfl_down_sync(0xffffffffu, dq, o);
    }
    const int w = tid >> 5, ln = tid & 31;
    if (ln == 0) { wa[w] = da; wq[w] = dq; }
    __syncthreads();
    if (tid == 0) {
        double A = 0.0, Q = 0.0;
        #pragma unroll
        for (int i = 0; i < 8; i++) { A += wa[i]; Q += wq[i]; }
        g_pabs[r] = A;
        g_psq[r]  = Q;
    }
}

// ---------------- kernel 2: global threshold ----------------
__global__ __launch_bounds__(256) void thr_kernel() {
    __shared__ double wa[8], wq[8];
    const int tid = threadIdx.x;
    double da = 0.0, dq = 0.0;
    for (int i = tid; i < B_ROWS; i += 256) { da += g_pabs[i]; dq += g_psq[i]; }
    #pragma unroll
    for (int o = 16; o > 0; o >>= 1) {
        da += __shfl_down_sync(0xffffffffu, da, o);
        dq += __shfl_down_sync(0xffffffffu, dq, o);
    }
    const int w = tid >> 5, ln = tid & 31;
    if (ln == 0) { wa[w] = da; wq[w] = dq; }
    __syncthreads();
    if (tid == 0) {
        double A = 0.0, Q = 0.0;
        #pragma unroll
        for (int i = 0; i < 8; i++) { A += wa[i]; Q += wq[i]; }
        const double N = (double)B_ROWS * (double)L_DIM;
        double mean = A / N;
        double var  = (Q - N * mean * mean) / (N - 1.0);
        if (var < 0.0) var = 0.0;
        g_thr = (float)(mean + sqrt(var));
    }
}

// ---------------- kernel 3: Haar recompute + mask + fp16 store ----------------
__global__ __launch_bounds__(256) void haar_mask_kernel(const float* __restrict__ x) {
    __shared__ float s[4096];
    __shared__ __half o16[4096];

    const int r = blockIdx.x;
    const int tid = threadIdx.x;
    const float thr = g_thr;

    const float4* xr = reinterpret_cast<const float4*>(x + (size_t)r * L_DIM);
    float4* s4 = reinterpret_cast<float4*>(s);
    #pragma unroll
    for (int i = 0; i < 4; i++) s4[tid + i * 256] = xr[tid + i * 256];
    __syncthreads();

    #pragma unroll
    for (int lvl = 0; lvl < 5; lvl++) {
        const int half = 2048 >> lvl;
        float areg[8];
        #pragma unroll
        for (int it = 0; it < 8; it++) {
            const int t = tid + it * 256;
            if (t < half) {
                float2 eo = *reinterpret_cast<const float2*>(&s[2 * t]);
                float d = (eo.x - eo.y) * SQRT_HALF;
                float a = (eo.x + eo.y) * SQRT_HALF;
                float dm = (fabsf(d) > thr) ? d : 0.f;
                o16[half + t] = __float2half_rn(dm);
                areg[it] = a;
            }
        }
        __syncthreads();
        #pragma unroll
        for (int it = 0; it < 8; it++) {
            const int t = tid + it * 256;
            if (t < half) s[t] = areg[it];
        }
        __syncthreads();
    }
    if (tid < 128) {
        float a = s[tid];
        float am = (fabsf(a) > thr) ? a : 0.f;
        o16[tid] = __float2half_rn(am);
    }
    __syncthreads();

    const uint4* src = reinterpret_cast<const uint4*>(o16);
    uint4* dst = reinterpret_cast<uint4*>(g_A16 + (size_t)r * L_DIM);
    #pragma unroll
    for (int i = 0; i < 2; i++) dst[tid + i * 256] = src[tid + i * 256];
}

// ---------------- kernel 4: B transpose + fp16 convert ----------------
__global__ __launch_bounds__(256) void bconv_kernel(const float* __restrict__ Bm) {
    __shared__ float t[64][65];
    const int n0 = blockIdx.x * 64;
    const int k0 = blockIdx.y * 64;
    for (int idx = threadIdx.x; idx < 4096; idx += 256) {
        int r = idx >> 6, c = idx & 63;           // r = k, c = n
        t[r][c] = Bm[(size_t)(k0 + r) * OUT_DIM + n0 + c];
    }
    __syncthreads();
    for (int idx = threadIdx.x; idx < 4096; idx += 256) {
        int n = idx >> 6, kk = idx & 63;
        g_B16[(size_t)(n0 + n) * L_DIM + k0 + kk] = __float2half_rn(t[kk][n]);
    }
}

// ---------------- kernel 5: fp16 HMMA GEMM + ReLU (TMA tensor, 3-stage) ----------------
// CTA 128(m) x 256(n) x 64(k), 512 threads, 16 warps = 4m x 4n, warp tile 32x64.
// 2 TMA tensor loads per stage (SW128-swizzled), mbarrier tx accounting.
#define BM 128
#define BN 256
#define BK 64
#define NST (L_DIM / BK)
#define A_TSZ 16384                                /* 128 rows x 128B */
#define B_TSZ 32768                                /* 256 rows x 128B */
#define ST_SZ (A_TSZ + B_TSZ)                      /* 49152 */
#define OFF_A(b) ((b) * ST_SZ)
#define OFF_B(b) ((b) * ST_SZ + A_TSZ)
#define MBAR_OFF (3 * ST_SZ)                       /* 147456 */
#define SMEM_TOTAL (3 * ST_SZ + 64)

__global__ void __launch_bounds__(512, 1) gemm_kernel(
        float* __restrict__ out,
        const __grid_constant__ CUtensorMap ta,
        const __grid_constant__ CUtensorMap tb) {
    extern __shared__ char smem[];
    const uint32_t sb = smem_u32(smem);
    const int tid = threadIdx.x;
    const int lane = tid & 31;
    const int wid = tid >> 5;
    const int bm = blockIdx.y * BM;
    const int bn = blockIdx.x * BN;

    const int wm = (wid >> 2) * 32;               // warp m-offset
    const int wn = (wid & 3) * 64;                // warp n-offset

    if (tid == 0) {
        mbar_init(sb + MBAR_OFF + 0, 1);
        mbar_init(sb + MBAR_OFF + 8, 1);
        mbar_init(sb + MBAR_OFF + 16, 1);
        asm volatile("fence.proxy.async.shared::cta;" ::: "memory");
    }
    __syncthreads();

    float acc[2][8][4];
    #pragma unroll
    for (int i = 0; i < 2; i++)
        #pragma unroll
        for (int j = 0; j < 8; j++)
            #pragma unroll
            for (int q = 0; q < 4; q++) acc[i][j][q] = 0.f;

    auto fill = [&](int t) {
        if (tid == 0) {
            const int buf = t % 3;
            const uint32_t mb = sb + MBAR_OFF + buf * 8;
            mbar_expect(mb, ST_SZ);
            tma2d(sb + OFF_A(buf), &ta, t * BK, bm, mb);
            tma2d(sb + OFF_B(buf), &tb, t * BK, bn, mb);
        }
    };

    fill(0);
    fill(1);

    const uint32_t sxor = (uint32_t)(lane & 7) << 4;   // SW128 swizzle xor (row&7)<<4
    const uint32_t ar = wm + (lane & 15);
    const uint32_t br = ((lane >> 4) << 3) + (lane & 7);

    for (int s = 0; s < NST; s++) {
        const int b = s % 3;

        if (s + 2 < NST) fill(s + 2);

        mbar_wait(sb + MBAR_OFF + b * 8, (uint32_t)((s / 3) & 1));

        const uint32_t sAH = sb + OFF_A(b);
        const uint32_t sBH = sb + OFF_B(b);
        #pragma unroll
        for (int ks = 0; ks < 4; ks++) {
            const uint32_t ac = ((uint32_t)(ks * 32) + ((uint32_t)(lane >> 4) << 4)) ^ sxor;
            const uint32_t bc = ((uint32_t)(ks * 32) + (((uint32_t)(lane >> 3) & 1) << 4)) ^ sxor;

            uint32_t bh[4][4];
            #pragma unroll
            for (int g = 0; g < 4; g++)
                ldsm4(bh[g], sBH + (wn + g * 16 + br) * 128 + bc);

            uint32_t ah[2][4];
            ldsm4(ah[0], sAH + ar * 128 + ac);
            ldsm4(ah[1], sAH + (ar + 16) * 128 + ac);

            #pragma unroll
            for (int mf = 0; mf < 2; mf++)
                #pragma unroll
                for (int g = 0; g < 4; g++) {
                    mma16816(acc[mf][2 * g],     ah[mf], &bh[g][0]);
                    mma16816(acc[mf][2 * g + 1], ah[mf], &bh[g][2]);
                }
        }

        __syncthreads();
    }

    // ---- epilogue: ReLU + store ----
    const int g  = lane >> 2;
    const int tq = lane & 3;
    #pragma unroll
    for (int mf = 0; mf < 2; mf++) {
        #pragma unroll
        for (int nf = 0; nf < 8; nf++) {
            const int m0 = bm + wm + mf * 16 + g;
            const int n0 = bn + wn + nf * 8 + tq * 2;
            float2 v0, v1;
            v0.x = fmaxf(acc[mf][nf][0], 0.f);
            v0.y = fmaxf(acc[mf][nf][1], 0.f);
            v1.x = fmaxf(acc[mf][nf][2], 0.f);
            v1.y = fmaxf(acc[mf][nf][3], 0.f);
            *reinterpret_cast<float2*>(out + (size_t)m0 * OUT_DIM + n0) = v0;
            *reinterpret_cast<float2*>(out + (size_t)(m0 + 8) * OUT_DIM + n0) = v1;
        }
    }
}

// ---------------- launcher ----------------
typedef CUresult (*PFN_encTiled)(CUtensorMap*, CUtensorMapDataType, cuuint32_t, void*,
                                 const cuuint64_t*, const cuuint64_t*, const cuuint32_t*,
                                 const cuuint32_t*, CUtensorMapInterleave, CUtensorMapSwizzle,
                                 CUtensorMapL2promotion, CUtensorMapFloatOOBfill);

extern "C" void kernel_launch(void* const* d_in, const int* in_sizes, int n_in,
                              void* d_out, int out_size) {
    const float* x  = (const float*)d_in[0];     // (8192, 1, 4096) fp32
    const float* bm = (const float*)d_in[1];     // (4096, 512) fp32
    float* out = (float*)d_out;                  // (8192, 1, 512) fp32

    cudaFuncSetAttribute(gemm_kernel, cudaFuncAttributeMaxDynamicSharedMemorySize, SMEM_TOTAL);

    // build TMA descriptors (host-side; runs at capture time only)
    void *pa = nullptr, *pb = nullptr;
    cudaGetSymbolAddress(&pa, g_A16);
    cudaGetSymbolAddress(&pb, g_B16);
    PFN_encTiled enc = nullptr;
    cudaDriverEntryPointQueryResult qr;
    cudaGetDriverEntryPoint("cuTensorMapEncodeTiled", (void**)&enc, cudaEnableDefault, &qr);

    CUtensorMap ta, tb;
    {
        cuuint64_t dims[2] = {L_DIM, B_ROWS};
        cuuint64_t str[1]  = {L_DIM * 2};
        cuuint32_t box[2]  = {64, 128};
        cuuint32_t es[2]   = {1, 1};
        enc(&ta, CU_TENSOR_MAP_DATA_TYPE_FLOAT16, 2, pa, dims, str, box, es,
            CU_TENSOR_MAP_INTERLEAVE_NONE, CU_TENSOR_MAP_SWIZZLE_128B,
            CU_TENSOR_MAP_L2_PROMOTION_L2_128B, CU_TENSOR_MAP_FLOAT_OOB_FILL_NONE);
    }
    {
        cuuint64_t dims[2] = {L_DIM, OUT_DIM};
        cuuint64_t str[1]  = {L_DIM * 2};
        cuuint32_t box[2]  = {64, 256};
        cuuint32_t es[2]   = {1, 1};
        enc(&tb, CU_TENSOR_MAP_DATA_TYPE_FLOAT16, 2, pb, dims, str, box, es,
            CU_TENSOR_MAP_INTERLEAVE_NONE, CU_TENSOR_MAP_SWIZZLE_128B,
            CU_TENSOR_MAP_L2_PROMOTION_L2_128B, CU_TENSOR_MAP_FLOAT_OOB_FILL_NONE);
    }

    haar_stats_kernel<<<B_ROWS, 256>>>(x);
    thr_kernel<<<1, 256>>>();
    bconv_kernel<<<dim3(OUT_DIM / 64, L_DIM / 64), 256>>>(bm);
    haar_mask_kernel<<<B_ROWS, 256>>>(x);
    gemm_kernel<<<dim3(OUT_DIM / BN, B_ROWS / BM), 512, SMEM_TOTAL>>>(out, ta, tb);
}

// round 15
// speedup vs baseline: 1.2676x; 1.0138x over previous
#include <cuda_runtime.h>
#include <cuda_fp16.h>
#include <cuda.h>
#include <cstdint>

#define B_ROWS 8192
#define L_DIM  4096
#define OUT_DIM 512
#define SQRT_HALF 0.7071067811865476f

// ---------------- scratch (static __device__, no allocation) ----------------
__device__ __align__(128) __half g_A16[(size_t)B_ROWS * L_DIM];  // masked fp16 A
__device__ __align__(128) __half g_B16[(size_t)OUT_DIM * L_DIM]; // B^T fp16 [n][k]
__device__ double g_pabs[B_ROWS];
__device__ double g_psq[B_ROWS];
__device__ float  g_thr;

// ---------------- PTX helpers ----------------
__device__ __forceinline__ uint32_t smem_u32(const void* p) {
    uint32_t a;
    asm("{ .reg .u64 t; cvta.to.shared.u64 t, %1; cvt.u32.u64 %0, t; }" : "=r"(a) : "l"(p));
    return a;
}
__device__ __forceinline__ void ldsm4(uint32_t* r, uint32_t addr) {
    asm volatile("ldmatrix.sync.aligned.m8n8.x4.shared.b16 {%0,%1,%2,%3}, [%4];"
                 : "=r"(r[0]), "=r"(r[1]), "=r"(r[2]), "=r"(r[3]) : "r"(addr));
}
__device__ __forceinline__ void mma16816(float* c, const uint32_t* a, const uint32_t* b) {
    asm volatile("mma.sync.aligned.m16n8k16.row.col.f32.f16.f16.f32 "
                 "{%0,%1,%2,%3}, {%4,%5,%6,%7}, {%8,%9}, {%0,%1,%2,%3};"
                 : "+f"(c[0]), "+f"(c[1]), "+f"(c[2]), "+f"(c[3])
                 : "r"(a[0]), "r"(a[1]), "r"(a[2]), "r"(a[3]), "r"(b[0]), "r"(b[1]));
}
__device__ __forceinline__ void tma2d(uint32_t dst, const CUtensorMap* map,
                                      int cx, int cy, uint32_t mbar) {
    asm volatile("cp.async.bulk.tensor.2d.shared::cluster.global.tile.mbarrier::complete_tx::bytes "
                 "[%0], [%1, {%2, %3}], [%4];"
                 :: "r"(dst), "l"(map), "r"(cx), "r"(cy), "r"(mbar) : "memory");
}
__device__ __forceinline__ void mbar_init(uint32_t a, uint32_t c) {
    asm volatile("mbarrier.init.shared.b64 [%0], %1;" :: "r"(a), "r"(c) : "memory");
}
__device__ __forceinline__ void mbar_expect(uint32_t a, uint32_t bytes) {
    asm volatile("mbarrier.arrive.expect_tx.shared.b64 _, [%0], %1;" :: "r"(a), "r"(bytes) : "memory");
}
__device__ __forceinline__ void mbar_wait(uint32_t mbar, uint32_t parity) {
    uint32_t done;
    asm volatile("{\n\t.reg .pred p;\n\tmbarrier.try_wait.parity.acquire.cta.shared::cta.b64 p, [%1], %2;\n\tselp.b32 %0, 1, 0, p;\n\t}"
                 : "=r"(done) : "r"(mbar), "r"(parity) : "memory");
    if (!done) {
        asm volatile("{\n\t.reg .pred P1;\n\tWL_%=:\n\tmbarrier.try_wait.parity.acquire.cta.shared::cta.b64 P1, [%0], %1, 0x989680;\n\t@P1 bra.uni WD_%=;\n\tbra.uni WL_%=;\n\tWD_%=:\n\t}"
                     :: "r"(mbar), "r"(parity) : "memory");
    }
}

// ---------------- kernel 1: Haar DWT, stats ONLY ----------------
__global__ __launch_bounds__(256) void haar_stats_kernel(const float* __restrict__ x) {
    __shared__ float s[4096];
    __shared__ double wa[8], wq[8];

    const int r = blockIdx.x;
    const int tid = threadIdx.x;

    const float4* xr = reinterpret_cast<const float4*>(x + (size_t)r * L_DIM);
    float4* s4 = reinterpret_cast<float4*>(s);
    #pragma unroll
    for (int i = 0; i < 4; i++) s4[tid + i * 256] = xr[tid + i * 256];
    __syncthreads();

    float sabs = 0.f, ssq = 0.f;

    #pragma unroll
    for (int lvl = 0; lvl < 5; lvl++) {
        const int half = 2048 >> lvl;
        float areg[8];
        #pragma unroll
        for (int it = 0; it < 8; it++) {
            const int t = tid + it * 256;
            if (t < half) {
                float2 eo = *reinterpret_cast<const float2*>(&s[2 * t]);
                float d = (eo.x - eo.y) * SQRT_HALF;
                float a = (eo.x + eo.y) * SQRT_HALF;
                sabs += fabsf(d);
                ssq  += d * d;
                areg[it] = a;
            }
        }
        __syncthreads();
        #pragma unroll
        for (int it = 0; it < 8; it++) {
            const int t = tid + it * 256;
            if (t < half) s[t] = areg[it];
        }
        __syncthreads();
    }
    if (tid < 128) {
        float a = s[tid];
        sabs += fabsf(a);
        ssq  += a * a;
    }

    double da = (double)sabs, dq = (double)ssq;
    #pragma unroll
    for (int o = 16; o > 0; o >>= 1) {
        da += __shfl_down_sync(0xffffffffu, da, o);
        dq += __shfl_down_sync(0xffffffffu, dq, o);
    }
    const int w = tid >> 5, ln = tid & 31;
    if (ln == 0) { wa[w] = da; wq[w] = dq; }
    __syncthreads();
    if (tid == 0) {
        double A = 0.0, Q = 0.0;
        #pragma unroll
        for (int i = 0; i < 8; i++) { A += wa[i]; Q += wq[i]; }
        g_pabs[r] = A;
        g_psq[r]  = Q;
    }
}

// ---------------- kernel 2: global threshold ----------------
__global__ __launch_bounds__(256) void thr_kernel() {
    __shared__ double wa[8], wq[8];
    const int tid = threadIdx.x;
    double da = 0.0, dq = 0.0;
    for (int i = tid; i < B_ROWS; i += 256) { da += g_pabs[i]; dq += g_psq[i]; }
    #pragma unroll
    for (int o = 16; o > 0; o >>= 1) {
        da += __shfl_down_sync(0xffffffffu, da, o);
        dq += __shfl_down_sync(0xffffffffu, dq, o);
    }
    const int w = tid >> 5, ln = tid & 31;
    if (ln == 0) { wa[w] = da; wq[w] = dq; }
    __syncthreads();
    if (tid == 0) {
        double A = 0.0, Q = 0.0;
        #pragma unroll
        for (int i = 0; i < 8; i++) { A += wa[i]; Q += wq[i]; }
        const double N = (double)B_ROWS * (double)L_DIM;
        double mean = A / N;
        double var  = (Q - N * mean * mean) / (N - 1.0);
        if (var < 0.0) var = 0.0;
        g_thr = (float)(mean + sqrt(var));
    }
}

// ---------------- kernel 3: Haar recompute + mask + fp16 store ----------------
__global__ __launch_bounds__(256) void haar_mask_kernel(const float* __restrict__ x) {
    __shared__ float s[4096];
    __shared__ __half o16[4096];

    const int r = blockIdx.x;
    const int tid = threadIdx.x;
    const float thr = g_thr;

    const float4* xr = reinterpret_cast<const float4*>(x + (size_t)r * L_DIM);
    float4* s4 = reinterpret_cast<float4*>(s);
    #pragma unroll
    for (int i = 0; i < 4; i++) s4[tid + i * 256] = xr[tid + i * 256];
    __syncthreads();

    #pragma unroll
    for (int lvl = 0; lvl < 5; lvl++) {
        const int half = 2048 >> lvl;
        float areg[8];
        #pragma unroll
        for (int it = 0; it < 8; it++) {
            const int t = tid + it * 256;
            if (t < half) {
                float2 eo = *reinterpret_cast<const float2*>(&s[2 * t]);
                float d = (eo.x - eo.y) * SQRT_HALF;
                float a = (eo.x + eo.y) * SQRT_HALF;
                float dm = (fabsf(d) > thr) ? d : 0.f;
                o16[half + t] = __float2half_rn(dm);
                areg[it] = a;
            }
        }
        __syncthreads();
        #pragma unroll
        for (int it = 0; it < 8; it++) {
            const int t = tid + it * 256;
            if (t < half) s[t] = areg[it];
        }
        __syncthreads();
    }
    if (tid < 128) {
        float a = s[tid];
        float am = (fabsf(a) > thr) ? a : 0.f;
        o16[tid] = __float2half_rn(am);
    }
    __syncthreads();

    const uint4* src = reinterpret_cast<const uint4*>(o16);
    uint4* dst = reinterpret_cast<uint4*>(g_A16 + (size_t)r * L_DIM);
    #pragma unroll
    for (int i = 0; i < 2; i++) dst[tid + i * 256] = src[tid + i * 256];
}

// ---------------- kernel 4: B transpose + fp16 convert ----------------
__global__ __launch_bounds__(256) void bconv_kernel(const float* __restrict__ Bm) {
    __shared__ float t[64][65];
    const int n0 = blockIdx.x * 64;
    const int k0 = blockIdx.y * 64;
    for (int idx = threadIdx.x; idx < 4096; idx += 256) {
        int r = idx >> 6, c = idx & 63;           // r = k, c = n
        t[r][c] = Bm[(size_t)(k0 + r) * OUT_DIM + n0 + c];
    }
    __syncthreads();
    for (int idx = threadIdx.x; idx < 4096; idx += 256) {
        int n = idx >> 6, kk = idx & 63;
        g_B16[(size_t)(n0 + n) * L_DIM + k0 + kk] = __float2half_rn(t[kk][n]);
    }
}

// ---------------- kernel 5: fp16 HMMA GEMM + ReLU (TMA, 3-stage, 2 CTA/SM) ----------------
// CTA 128(m) x 128(n) x 64(k), 256 threads, 8 warps = 4m x 2n, warp tile 32x64.
#define BM 128
#define BN 128
#define BK 64
#define NST (L_DIM / BK)
#define A_TSZ 16384                                /* 128 rows x 128B */
#define B_TSZ 16384                                /* 128 rows x 128B */
#define ST_SZ (A_TSZ + B_TSZ)                      /* 32768 */
#define OFF_A(b) ((b) * ST_SZ)
#define OFF_B(b) ((b) * ST_SZ + A_TSZ)
#define MBAR_OFF (3 * ST_SZ)                       /* 98304 */
#define SMEM_TOTAL (3 * ST_SZ + 64)                /* 98368 -> 2 CTAs/SM */

__global__ void __launch_bounds__(256, 2) gemm_kernel(
        float* __restrict__ out,
        const __grid_constant__ CUtensorMap ta,
        const __grid_constant__ CUtensorMap tb) {
    extern __shared__ char smem[];
    const uint32_t sb = smem_u32(smem);
    const int tid = threadIdx.x;
    const int lane = tid & 31;
    const int wid = tid >> 5;
    const int bm = blockIdx.y * BM;
    const int bn = blockIdx.x * BN;

    const int wm = (wid >> 1) * 32;               // warp m-offset (0,32,64,96)
    const int wn = (wid & 1) * 64;                // warp n-offset (0,64)

    if (tid == 0) {
        mbar_init(sb + MBAR_OFF + 0, 1);
        mbar_init(sb + MBAR_OFF + 8, 1);
        mbar_init(sb + MBAR_OFF + 16, 1);
        asm volatile("fence.proxy.async.shared::cta;" ::: "memory");
    }
    __syncthreads();

    float acc[2][8][4];
    #pragma unroll
    for (int i = 0; i < 2; i++)
        #pragma unroll
        for (int j = 0; j < 8; j++)
            #pragma unroll
            for (int q = 0; q < 4; q++) acc[i][j][q] = 0.f;

    auto fill = [&](int t) {
        if (tid == 0) {
            const int buf = t % 3;
            const uint32_t mb = sb + MBAR_OFF + buf * 8;
            mbar_expect(mb, ST_SZ);
            tma2d(sb + OFF_A(buf), &ta, t * BK, bm, mb);
            tma2d(sb + OFF_B(buf), &tb, t * BK, bn, mb);
        }
    };

    fill(0);
    fill(1);

    const uint32_t sxor = (uint32_t)(lane & 7) << 4;   // SW128 swizzle xor
    const uint32_t ar = wm + (lane & 15);
    const uint32_t br = ((lane >> 4) << 3) + (lane & 7);

    for (int s = 0; s < NST; s++) {
        const int b = s % 3;

        if (s + 2 < NST) fill(s + 2);

        mbar_wait(sb + MBAR_OFF + b * 8, (uint32_t)((s / 3) & 1));

        const uint32_t sAH = sb + OFF_A(b);
        const uint32_t sBH = sb + OFF_B(b);
        #pragma unroll
        for (int ks = 0; ks < 4; ks++) {
            const uint32_t ac = ((uint32_t)(ks * 32) + ((uint32_t)(lane >> 4) << 4)) ^ sxor;
            const uint32_t bc = ((uint32_t)(ks * 32) + (((uint32_t)(lane >> 3) & 1) << 4)) ^ sxor;

            uint32_t bh[4][4];
            #pragma unroll
            for (int g = 0; g < 4; g++)
                ldsm4(bh[g], sBH + (wn + g * 16 + br) * 128 + bc);

            uint32_t ah[2][4];
            ldsm4(ah[0], sAH + ar * 128 + ac);
            ldsm4(ah[1], sAH + (ar + 16) * 128 + ac);

            #pragma unroll
            for (int mf = 0; mf < 2; mf++)
                #pragma unroll
                for (int g = 0; g < 4; g++) {
                    mma16816(acc[mf][2 * g],     ah[mf], &bh[g][0]);
                    mma16816(acc[mf][2 * g + 1], ah[mf], &bh[g][2]);
                }
        }

        __syncthreads();
    }

    // ---- epilogue: ReLU + store ----
    const int g  = lane >> 2;
    const int tq = lane & 3;
    #pragma unroll
    for (int mf = 0; mf < 2; mf++) {
        #pragma unroll
        for (int nf = 0; nf < 8; nf++) {
            const int m0 = bm + wm + mf * 16 + g;
            const int n0 = bn + wn + nf * 8 + tq * 2;
            float2 v0, v1;
            v0.x = fmaxf(acc[mf][nf][0], 0.f);
            v0.y = fmaxf(acc[mf][nf][1], 0.f);
            v1.x = fmaxf(acc[mf][nf][2], 0.f);
            v1.y = fmaxf(acc[mf][nf][3], 0.f);
            *reinterpret_cast<float2*>(out + (size_t)m0 * OUT_DIM + n0) = v0;
            *reinterpret_cast<float2*>(out + (size_t)(m0 + 8) * OUT_DIM + n0) = v1;
        }
    }
}

// ---------------- launcher ----------------
typedef CUresult (*PFN_encTiled)(CUtensorMap*, CUtensorMapDataType, cuuint32_t, void*,
                                 const cuuint64_t*, const cuuint64_t*, const cuuint32_t*,
                                 const cuuint32_t*, CUtensorMapInterleave, CUtensorMapSwizzle,
                                 CUtensorMapL2promotion, CUtensorMapFloatOOBfill);

extern "C" void kernel_launch(void* const* d_in, const int* in_sizes, int n_in,
                              void* d_out, int out_size) {
    const float* x  = (const float*)d_in[0];     // (8192, 1, 4096) fp32
    const float* bm = (const float*)d_in[1];     // (4096, 512) fp32
    float* out = (float*)d_out;                  // (8192, 1, 512) fp32

    cudaFuncSetAttribute(gemm_kernel, cudaFuncAttributeMaxDynamicSharedMemorySize, SMEM_TOTAL);

    void *pa = nullptr, *pb = nullptr;
    cudaGetSymbolAddress(&pa, g_A16);
    cudaGetSymbolAddress(&pb, g_B16);
    PFN_encTiled enc = nullptr;
    cudaDriverEntryPointQueryResult qr;
    cudaGetDriverEntryPoint("cuTensorMapEncodeTiled", (void**)&enc, cudaEnableDefault, &qr);

    CUtensorMap ta, tb;
    {
        cuuint64_t dims[2] = {L_DIM, B_ROWS};
        cuuint64_t str[1]  = {L_DIM * 2};
        cuuint32_t box[2]  = {64, 128};
        cuuint32_t es[2]   = {1, 1};
        enc(&ta, CU_TENSOR_MAP_DATA_TYPE_FLOAT16, 2, pa, dims, str, box, es,
            CU_TENSOR_MAP_INTERLEAVE_NONE, CU_TENSOR_MAP_SWIZZLE_128B,
            CU_TENSOR_MAP_L2_PROMOTION_L2_128B, CU_TENSOR_MAP_FLOAT_OOB_FILL_NONE);
    }
    {
        cuuint64_t dims[2] = {L_DIM, OUT_DIM};
        cuuint64_t str[1]  = {L_DIM * 2};
        cuuint32_t box[2]  = {64, 128};
        cuuint32_t es[2]   = {1, 1};
        enc(&tb, CU_TENSOR_MAP_DATA_TYPE_FLOAT16, 2, pb, dims, str, box, es,
            CU_TENSOR_MAP_INTERLEAVE_NONE, CU_TENSOR_MAP_SWIZZLE_128B,
            CU_TENSOR_MAP_L2_PROMOTION_L2_128B, CU_TENSOR_MAP_FLOAT_OOB_FILL_NONE);
    }

    haar_stats_kernel<<<B_ROWS, 256>>>(x);
    thr_kernel<<<1, 256>>>();
    bconv_kernel<<<dim3(OUT_DIM / 64, L_DIM / 64), 256>>>(bm);
    haar_mask_kernel<<<B_ROWS, 256>>>(x);
    gemm_kernel<<<dim3(OUT_DIM / BN, B_ROWS / BM), 256, SMEM_TOTAL>>>(out, ta, tb);
}

// round 17
// speedup vs baseline: 1.3570x; 1.0705x over previous
#include <cuda_runtime.h>
#include <cuda_fp16.h>
#include <cuda.h>
#include <cstdint>

#define B_ROWS 8192
#define L_DIM  4096
#define OUT_DIM 512
#define SQRT_HALF 0.7071067811865476f

// ---------------- scratch (static __device__, no allocation) ----------------
__device__ __align__(128) __half g_A16[(size_t)B_ROWS * L_DIM];  // masked fp16 coeffs
__device__ __align__(128) __half g_B16[(size_t)OUT_DIM * L_DIM]; // B^T fp16 [n][k]
__device__ double g_pabs[B_ROWS];
__device__ double g_psq[B_ROWS];
__device__ float  g_thr;

// ---------------- PTX helpers ----------------
__device__ __forceinline__ uint32_t smem_u32(const void* p) {
    uint32_t a;
    asm("{ .reg .u64 t; cvta.to.shared.u64 t, %1; cvt.u32.u64 %0, t; }" : "=r"(a) : "l"(p));
    return a;
}
__device__ __forceinline__ void ldsm4(uint32_t* r, uint32_t addr) {
    asm volatile("ldmatrix.sync.aligned.m8n8.x4.shared.b16 {%0,%1,%2,%3}, [%4];"
                 : "=r"(r[0]), "=r"(r[1]), "=r"(r[2]), "=r"(r[3]) : "r"(addr));
}
__device__ __forceinline__ void mma16816(float* c, const uint32_t* a, const uint32_t* b) {
    asm volatile("mma.sync.aligned.m16n8k16.row.col.f32.f16.f16.f32 "
                 "{%0,%1,%2,%3}, {%4,%5,%6,%7}, {%8,%9}, {%0,%1,%2,%3};"
                 : "+f"(c[0]), "+f"(c[1]), "+f"(c[2]), "+f"(c[3])
                 : "r"(a[0]), "r"(a[1]), "r"(a[2]), "r"(a[3]), "r"(b[0]), "r"(b[1]));
}
__device__ __forceinline__ void tma2d(uint32_t dst, const CUtensorMap* map,
                                      int cx, int cy, uint32_t mbar) {
    asm volatile("cp.async.bulk.tensor.2d.shared::cluster.global.tile.mbarrier::complete_tx::bytes "
                 "[%0], [%1, {%2, %3}], [%4];"
                 :: "r"(dst), "l"(map), "r"(cx), "r"(cy), "r"(mbar) : "memory");
}
__device__ __forceinline__ void mbar_init(uint32_t a, uint32_t c) {
    asm volatile("mbarrier.init.shared.b64 [%0], %1;" :: "r"(a), "r"(c) : "memory");
}
__device__ __forceinline__ void mbar_expect(uint32_t a, uint32_t bytes) {
    asm volatile("mbarrier.arrive.expect_tx.shared.b64 _, [%0], %1;" :: "r"(a), "r"(bytes) : "memory");
}
__device__ __forceinline__ void mbar_wait(uint32_t mbar, uint32_t parity) {
    uint32_t done;
    asm volatile("{\n\t.reg .pred p;\n\tmbarrier.try_wait.parity.acquire.cta.shared::cta.b64 p, [%1], %2;\n\tselp.b32 %0, 1, 0, p;\n\t}"
                 : "=r"(done) : "r"(mbar), "r"(parity) : "memory");
    if (!done) {
        asm volatile("{\n\t.reg .pred P1;\n\tWL_%=:\n\tmbarrier.try_wait.parity.acquire.cta.shared::cta.b64 P1, [%0], %1, 0x989680;\n\t@P1 bra.uni WD_%=;\n\tbra.uni WL_%=;\n\tWD_%=:\n\t}"
                     :: "r"(mbar), "r"(parity) : "memory");
    }
}
__device__ __forceinline__ uint32_t packh(float a, float b) {
    __half2 h = __floats2half2_rn(a, b);
    return *reinterpret_cast<uint32_t*>(&h);
}

// ---------------- kernel 1: Haar stats (level-1 in registers) ----------------
__global__ __launch_bounds__(256) void haar_stats_kernel(const float* __restrict__ x) {
    __shared__ float s[2048];                 // approx pyramid only
    __shared__ double wa[8], wq[8];

    const int r = blockIdx.x;
    const int tid = threadIdx.x;

    float sabs = 0.f, ssq = 0.f;

    // level 1 in registers: thread handles float4s f = tid + i*256
    const float4* xr = reinterpret_cast<const float4*>(x + (size_t)r * L_DIM);
    #pragma unroll
    for (int i = 0; i < 4; i++) {
        const int f = tid + i * 256;
        float4 v = xr[f];
        float d0 = (v.x - v.y) * SQRT_HALF;
        float a0 = (v.x + v.y) * SQRT_HALF;
        float d1 = (v.z - v.w) * SQRT_HALF;
        float a1 = (v.z + v.w) * SQRT_HALF;
        sabs += fabsf(d0) + fabsf(d1);
        ssq  += d0 * d0 + d1 * d1;
        *reinterpret_cast<float2*>(&s[2 * f]) = make_float2(a0, a1);
    }
    __syncthreads();

    // levels 2..5 on smem (approx length 2048 -> 128)
    #pragma unroll
    for (int lvl = 1; lvl < 5; lvl++) {
        const int half = 2048 >> lvl;         // 1024,512,256,128
        float areg[4];
        #pragma unroll
        for (int it = 0; it < 4; it++) {
            const int t = tid + it * 256;
            if (t < half) {
                float2 eo = *reinterpret_cast<const float2*>(&s[2 * t]);
                float d = (eo.x - eo.y) * SQRT_HALF;
                float a = (eo.x + eo.y) * SQRT_HALF;
                sabs += fabsf(d);
                ssq  += d * d;
                areg[it] = a;
            }
        }
        __syncthreads();
        #pragma unroll
        for (int it = 0; it < 4; it++) {
            const int t = tid + it * 256;
            if (t < half) s[t] = areg[it];
        }
        __syncthreads();
    }
    if (tid < 128) {
        float a = s[tid];
        sabs += fabsf(a);
        ssq  += a * a;
    }

    double da = (double)sabs, dq = (double)ssq;
    #pragma unroll
    for (int o = 16; o > 0; o >>= 1) {
        da += __shfl_down_sync(0xffffffffu, da, o);
        dq += __shfl_down_sync(0xffffffffu, dq, o);
    }
    const int w = tid >> 5, ln = tid & 31;
    if (ln == 0) { wa[w] = da; wq[w] = dq; }
    __syncthreads();
    if (tid == 0) {
        double A = 0.0, Q = 0.0;
        #pragma unroll
        for (int i = 0; i < 8; i++) { A += wa[i]; Q += wq[i]; }
        g_pabs[r] = A;
        g_psq[r]  = Q;
    }
}

// ---------------- kernel 2: global threshold ----------------
__global__ __launch_bounds__(256) void thr_kernel() {
    __shared__ double wa[8], wq[8];
    const int tid = threadIdx.x;
    double da = 0.0, dq = 0.0;
    for (int i = tid; i < B_ROWS; i += 256) { da += g_pabs[i]; dq += g_psq[i]; }
    #pragma unroll
    for (int o = 16; o > 0; o >>= 1) {
        da += __shfl_down_sync(0xffffffffu, da, o);
        dq += __shfl_down_sync(0xffffffffu, dq, o);
    }
    const int w = tid >> 5, ln = tid & 31;
    if (ln == 0) { wa[w] = da; wq[w] = dq; }
    __syncthreads();
    if (tid == 0) {
        double A = 0.0, Q = 0.0;
        #pragma unroll
        for (int i = 0; i < 8; i++) { A += wa[i]; Q += wq[i]; }
        const double N = (double)B_ROWS * (double)L_DIM;
        double mean = A / N;
        double var  = (Q - N * mean * mean) / (N - 1.0);
        if (var < 0.0) var = 0.0;
        g_thr = (float)(mean + sqrt(var));
    }
}

// ---------------- kernel 3: Haar recompute + fp32 mask + fp16 direct STG ----------------
__global__ __launch_bounds__(256) void haar_mask_kernel(const float* __restrict__ x) {
    __shared__ float s[2048];

    const int r = blockIdx.x;
    const int tid = threadIdx.x;
    const float thr = g_thr;
    __half* Ar = g_A16 + (size_t)r * L_DIM;

    // level 1 in registers; masked fp16 details written straight to gmem
    const float4* xr = reinterpret_cast<const float4*>(x + (size_t)r * L_DIM);
    #pragma unroll
    for (int i = 0; i < 4; i++) {
        const int f = tid + i * 256;
        float4 v = xr[f];
        float d0 = (v.x - v.y) * SQRT_HALF;
        float a0 = (v.x + v.y) * SQRT_HALF;
        float d1 = (v.z - v.w) * SQRT_HALF;
        float a1 = (v.z + v.w) * SQRT_HALF;
        d0 = (fabsf(d0) > thr) ? d0 : 0.f;    // mask on exact fp32
        d1 = (fabsf(d1) > thr) ? d1 : 0.f;
        *reinterpret_cast<uint32_t*>(&Ar[2048 + 2 * f]) = packh(d0, d1);
        *reinterpret_cast<float2*>(&s[2 * f]) = make_float2(a0, a1);
    }
    __syncthreads();

    #pragma unroll
    for (int lvl = 1; lvl < 5; lvl++) {
        const int half = 2048 >> lvl;
        float areg[4];
        #pragma unroll
        for (int it = 0; it < 4; it++) {
            const int t = tid + it * 256;
            if (t < half) {
                float2 eo = *reinterpret_cast<const float2*>(&s[2 * t]);
                float d = (eo.x - eo.y) * SQRT_HALF;
                float a = (eo.x + eo.y) * SQRT_HALF;
                d = (fabsf(d) > thr) ? d : 0.f;
                Ar[half + t] = __float2half_rn(d);
                areg[it] = a;
            }
        }
        __syncthreads();
        #pragma unroll
        for (int it = 0; it < 4; it++) {
            const int t = tid + it * 256;
            if (t < half) s[t] = areg[it];
        }
        __syncthreads();
    }
    if (tid < 128) {
        float a = s[tid];
        a = (fabsf(a) > thr) ? a : 0.f;
        Ar[tid] = __float2half_rn(a);
    }
}

// ---------------- kernel 4: B transpose + fp16 convert ----------------
__global__ __launch_bounds__(256) void bconv_kernel(const float* __restrict__ Bm) {
    __shared__ float t[64][65];
    const int n0 = blockIdx.x * 64;
    const int k0 = blockIdx.y * 64;
    for (int idx = threadIdx.x; idx < 4096; idx += 256) {
        int r = idx >> 6, c = idx & 63;
        t[r][c] = Bm[(size_t)(k0 + r) * OUT_DIM + n0 + c];
    }
    __syncthreads();
    for (int idx = threadIdx.x; idx < 4096; idx += 256) {
        int n = idx >> 6, kk = idx & 63;
        g_B16[(size_t)(n0 + n) * L_DIM + k0 + kk] = __float2half_rn(t[kk][n]);
    }
}

// ---------------- kernel 5: fp16 HMMA GEMM + ReLU (TMA, 3-stage, 2 CTA/SM) ----------------
#define BM 128
#define BN 128
#define BK 64
#define NST (L_DIM / BK)
#define A_TSZ 16384
#define B_TSZ 16384
#define ST_SZ (A_TSZ + B_TSZ)
#define OFF_A(b) ((b) * ST_SZ)
#define OFF_B(b) ((b) * ST_SZ + A_TSZ)
#define MBAR_OFF (3 * ST_SZ)
#define SMEM_TOTAL (3 * ST_SZ + 64)

__global__ void __launch_bounds__(256, 2) gemm_kernel(
        float* __restrict__ out,
        const __grid_constant__ CUtensorMap ta,
        const __grid_constant__ CUtensorMap tb) {
    extern __shared__ char smem[];
    const uint32_t sb = smem_u32(smem);
    const int tid = threadIdx.x;
    const int lane = tid & 31;
    const int wid = tid >> 5;
    const int bm = blockIdx.y * BM;
    const int bn = blockIdx.x * BN;

    const int wm = (wid >> 1) * 32;
    const int wn = (wid & 1) * 64;

    if (tid == 0) {
        mbar_init(sb + MBAR_OFF + 0, 1);
        mbar_init(sb + MBAR_OFF + 8, 1);
        mbar_init(sb + MBAR_OFF + 16, 1);
        asm volatile("fence.proxy.async.shared::cta;" ::: "memory");
    }
    __syncthreads();

    float acc[2][8][4];
    #pragma unroll
    for (int i = 0; i < 2; i++)
        #pragma unroll
        for (int j = 0; j < 8; j++)
            #pragma unroll
            for (int q = 0; q < 4; q++) acc[i][j][q] = 0.f;

    auto fill = [&](int t) {
        if (tid == 0) {
            const int buf = t % 3;
            const uint32_t mb = sb + MBAR_OFF + buf * 8;
            mbar_expect(mb, ST_SZ);
            tma2d(sb + OFF_A(buf), &ta, t * BK, bm, mb);
            tma2d(sb + OFF_B(buf), &tb, t * BK, bn, mb);
        }
    };

    fill(0);
    fill(1);

    const uint32_t sxor = (uint32_t)(lane & 7) << 4;
    const uint32_t ar = wm + (lane & 15);
    const uint32_t br = ((lane >> 4) << 3) + (lane & 7);

    for (int s = 0; s < NST; s++) {
        const int b = s % 3;

        if (s + 2 < NST) fill(s + 2);

        mbar_wait(sb + MBAR_OFF + b * 8, (uint32_t)((s / 3) & 1));

        const uint32_t sAH = sb + OFF_A(b);
        const uint32_t sBH = sb + OFF_B(b);
        #pragma unroll
        for (int ks = 0; ks < 4; ks++) {
            const uint32_t ac = ((uint32_t)(ks * 32) + ((uint32_t)(lane >> 4) << 4)) ^ sxor;
            const uint32_t bc = ((uint32_t)(ks * 32) + (((uint32_t)(lane >> 3) & 1) << 4)) ^ sxor;

            uint32_t bh[4][4];
            #pragma unroll
            for (int g = 0; g < 4; g++)
                ldsm4(bh[g], sBH + (wn + g * 16 + br) * 128 + bc);

            uint32_t ah[2][4];
            ldsm4(ah[0], sAH + ar * 128 + ac);
            ldsm4(ah[1], sAH + (ar + 16) * 128 + ac);

            #pragma unroll
            for (int mf = 0; mf < 2; mf++)
                #pragma unroll
                for (int g = 0; g < 4; g++) {
                    mma16816(acc[mf][2 * g],     ah[mf], &bh[g][0]);
                    mma16816(acc[mf][2 * g + 1], ah[mf], &bh[g][2]);
                }
        }

        __syncthreads();
    }

    // ---- epilogue: ReLU + store ----
    const int g  = lane >> 2;
    const int tq = lane & 3;
    #pragma unroll
    for (int mf = 0; mf < 2; mf++) {
        #pragma unroll
        for (int nf = 0; nf < 8; nf++) {
            const int m0 = bm + wm + mf * 16 + g;
            const int n0 = bn + wn + nf * 8 + tq * 2;
            float2 v0, v1;
            v0.x = fmaxf(acc[mf][nf][0], 0.f);
            v0.y = fmaxf(acc[mf][nf][1], 0.f);
            v1.x = fmaxf(acc[mf][nf][2], 0.f);
            v1.y = fmaxf(acc[mf][nf][3], 0.f);
            *reinterpret_cast<float2*>(out + (size_t)m0 * OUT_DIM + n0) = v0;
            *reinterpret_cast<float2*>(out + (size_t)(m0 + 8) * OUT_DIM + n0) = v1;
        }
    }
}

// ---------------- launcher ----------------
typedef CUresult (*PFN_encTiled)(CUtensorMap*, CUtensorMapDataType, cuuint32_t, void*,
                                 const cuuint64_t*, const cuuint64_t*, const cuuint32_t*,
                                 const cuuint32_t*, CUtensorMapInterleave, CUtensorMapSwizzle,
                                 CUtensorMapL2promotion, CUtensorMapFloatOOBfill);

extern "C" void kernel_launch(void* const* d_in, const int* in_sizes, int n_in,
                              void* d_out, int out_size) {
    const float* x  = (const float*)d_in[0];     // (8192, 1, 4096) fp32
    const float* bm = (const float*)d_in[1];     // (4096, 512) fp32
    float* out = (float*)d_out;                  // (8192, 1, 512) fp32

    cudaFuncSetAttribute(gemm_kernel, cudaFuncAttributeMaxDynamicSharedMemorySize, SMEM_TOTAL);

    void *pa = nullptr, *pb = nullptr;
    cudaGetSymbolAddress(&pa, g_A16);
    cudaGetSymbolAddress(&pb, g_B16);
    PFN_encTiled enc = nullptr;
    cudaDriverEntryPointQueryResult qr;
    cudaGetDriverEntryPoint("cuTensorMapEncodeTiled", (void**)&enc, cudaEnableDefault, &qr);

    CUtensorMap ta, tb;
    {
        cuuint64_t dims[2] = {L_DIM, B_ROWS};
        cuuint64_t str[1]  = {L_DIM * 2};
        cuuint32_t box[2]  = {64, 128};
        cuuint32_t es[2]   = {1, 1};
        enc(&ta, CU_TENSOR_MAP_DATA_TYPE_FLOAT16, 2, pa, dims, str, box, es,
            CU_TENSOR_MAP_INTERLEAVE_NONE, CU_TENSOR_MAP_SWIZZLE_128B,
            CU_TENSOR_MAP_L2_PROMOTION_L2_128B, CU_TENSOR_MAP_FLOAT_OOB_FILL_NONE);
    }
    {
        cuuint64_t dims[2] = {L_DIM, OUT_DIM};
        cuuint64_t str[1]  = {L_DIM * 2};
        cuuint32_t box[2]  = {64, 128};
        cuuint32_t es[2]   = {1, 1};
        enc(&tb, CU_TENSOR_MAP_DATA_TYPE_FLOAT16, 2, pb, dims, str, box, es,
            CU_TENSOR_MAP_INTERLEAVE_NONE, CU_TENSOR_MAP_SWIZZLE_128B,
            CU_TENSOR_MAP_L2_PROMOTION_L2_128B, CU_TENSOR_MAP_FLOAT_OOB_FILL_NONE);
    }

    haar_stats_kernel<<<B_ROWS, 256>>>(x);
    thr_kernel<<<1, 256>>>();
    bconv_kernel<<<dim3(OUT_DIM / 64, L_DIM / 64), 256>>>(bm);
    haar_mask_kernel<<<B_ROWS, 256>>>(x);
    gemm_kernel<<<dim3(OUT_DIM / BN, B_ROWS / BM), 256, SMEM_TOTAL>>>(out, ta, tb);
}